// round 10
// baseline (speedup 1.0000x reference)
#include <cuda_runtime.h>
#include <cfloat>

#define NPTS    65536
#define KNB     32
#define NSAMP   (NPTS * KNB)
#define CNT_INV (1.0f / 2097152.0f)
#define BN_EPS  1e-5f
#define GRID_MAIN 444

// g_acc float layout: C[9] | SG1[3] | SG2[6] | SN1[3] | SN2[6] | SF[32] | QF[32] | S2[64] | Q2[64]
#define OFF_C    0
#define OFF_SG1  9
#define OFF_SG2  12
#define OFF_SN1  18
#define OFF_SN2  21
#define OFF_SF   27
#define OFF_QF   59
#define OFF_S2   91
#define OFF_Q2   155
#define ACC_SZ   219

__device__ float  g_acc[ACC_SZ];
__device__ int    g_cnt[NPTS];
__device__ float  g_zmax[NPTS * 64];
__device__ float  g_zmin[NPTS * 64];
__device__ float4 g_stage1[160];            // layer1 folded weights, [i][5 float4] = 10 (w,w') pairs
__device__ float2 g_stage2[1024];           // layer2 weights, [i*32+l] = (W1[2l][i], W1[2l+1][i])

__device__ __forceinline__ void ffma2(float2& acc, float2 a, float2 b) {
#if defined(__CUDA_ARCH__) && (__CUDA_ARCH__ >= 1000)
    union { float2 f; unsigned long long u; } A, B, C;
    A.f = a; B.f = b; C.f = acc;
    asm("fma.rn.f32x2 %0, %1, %2, %0;" : "+l"(C.u) : "l"(A.u), "l"(B.u));
    acc = C.f;
#else
    acc.x = fmaf(a.x, b.x, acc.x);
    acc.y = fmaf(a.y, b.y, acc.y);
#endif
}

// ---------------- kernel 0: zero accumulators + histogram ----------------
__global__ void k_init() {
    const int t = blockIdx.x * blockDim.x + threadIdx.x;
    if (t < NPTS) g_cnt[t] = 0;
    if (t < ACC_SZ) g_acc[t] = 0.f;
}

// ---------------- kernel 1: histogram + cross term C = sum x_g x_n^T ----------------
__global__ __launch_bounds__(256)
void k_hc(const float* __restrict__ xyz, const int* __restrict__ gidx) {
    __shared__ float sC[9];
    const int tid = threadIdx.x;
    if (tid < 9) sC[tid] = 0.f;
    __syncthreads();

    const int t0     = blockIdx.x * blockDim.x + tid;
    const int stride = gridDim.x * blockDim.x;
    float C[9];
#pragma unroll
    for (int j = 0; j < 9; j++) C[j] = 0.f;

    for (int s = t0; s < NSAMP; s += stride) {
        const int g = gidx[s];
        atomicAdd(&g_cnt[g], 1);
        const int n = s >> 5;   // warp-uniform
        const float n0 = __ldg(&xyz[n * 3 + 0]);
        const float n1 = __ldg(&xyz[n * 3 + 1]);
        const float n2 = __ldg(&xyz[n * 3 + 2]);
        const float a0 = __ldg(&xyz[g * 3 + 0]);
        const float a1 = __ldg(&xyz[g * 3 + 1]);
        const float a2 = __ldg(&xyz[g * 3 + 2]);
        C[0] = fmaf(a0, n0, C[0]); C[1] = fmaf(a0, n1, C[1]); C[2] = fmaf(a0, n2, C[2]);
        C[3] = fmaf(a1, n0, C[3]); C[4] = fmaf(a1, n1, C[4]); C[5] = fmaf(a1, n2, C[5]);
        C[6] = fmaf(a2, n0, C[6]); C[7] = fmaf(a2, n1, C[7]); C[8] = fmaf(a2, n2, C[8]);
    }
#pragma unroll
    for (int j = 0; j < 9; j++)
#pragma unroll
        for (int o = 16; o > 0; o >>= 1) C[j] += __shfl_xor_sync(0xffffffffu, C[j], o);
    if ((tid & 31) == 0)
#pragma unroll
        for (int j = 0; j < 9; j++) atomicAdd(&sC[j], C[j]);
    __syncthreads();
    if (tid < 9) atomicAdd(&g_acc[OFF_C + tid], sC[tid]);
}

// ---------------- kernel 2: cnt-weighted moments over unique points ----------------
__global__ __launch_bounds__(256)
void k_mom(const float* __restrict__ xyz, const float* __restrict__ pts,
           const float* __restrict__ Wf0) {
    __shared__ float sA[82];
    const int tid = threadIdx.x;
    if (tid < 82) sA[tid] = 0.f;
    __syncthreads();

    const int g = blockIdx.x * blockDim.x + tid;   // exactly NPTS threads
    float a[82];
#pragma unroll
    for (int j = 0; j < 82; j++) a[j] = 0.f;

    if (g < NPTS) {
        const float w  = (float)g_cnt[g];
        const float x0 = xyz[g * 3 + 0], x1 = xyz[g * 3 + 1], x2 = xyz[g * 3 + 2];
        // sg1(0..2), sg2(3..8) as (00,01,02,11,12,22), sn1(9..11), sn2(12..17), sF(18..49), qF(50..81)
        a[0] = w * x0; a[1] = w * x1; a[2] = w * x2;
        a[3] = w * x0 * x0; a[4] = w * x0 * x1; a[5] = w * x0 * x2;
        a[6] = w * x1 * x1; a[7] = w * x1 * x2; a[8] = w * x2 * x2;
        a[9] = x0; a[10] = x1; a[11] = x2;
        a[12] = x0 * x0; a[13] = x0 * x1; a[14] = x0 * x2;
        a[15] = x1 * x1; a[16] = x1 * x2; a[17] = x2 * x2;
        float p[16];
        const float4* pr = (const float4*)pts + (size_t)g * 4;
#pragma unroll
        for (int q = 0; q < 4; q++) {
            const float4 v = __ldg(pr + q);
            p[q * 4 + 0] = v.x; p[q * 4 + 1] = v.y; p[q * 4 + 2] = v.z; p[q * 4 + 3] = v.w;
        }
#pragma unroll
        for (int i = 0; i < 32; i++) {
            float f = 0.f;
#pragma unroll
            for (int c = 0; c < 16; c++) f = fmaf(__ldg(&Wf0[i * 16 + c]), p[c], f);
            a[18 + i] = w * f;
            a[50 + i] = w * f * f;
        }
    }
#pragma unroll
    for (int j = 0; j < 82; j++)
#pragma unroll
        for (int o = 16; o > 0; o >>= 1) a[j] += __shfl_xor_sync(0xffffffffu, a[j], o);
    if ((tid & 31) == 0)
#pragma unroll
        for (int j = 0; j < 82; j++) atomicAdd(&sA[j], a[j]);
    __syncthreads();
    if (tid < 82) atomicAdd(&g_acc[OFF_SG1 + tid], sA[tid]);
}

// ---------------- kernel 3: fold BN1, stage weights ----------------
// Symmetric 3x3 pack order: (0,0)=0 (0,1)=1 (0,2)=2 (1,1)=3 (1,2)=4 (2,2)=5
__device__ __forceinline__ int symi(int aa, int bb) {
    const int lo = min(aa, bb), hi = max(aa, bb);
    return (lo == 0) ? hi : ((lo == 1) ? (2 + hi) : 5);
}

__global__ void k_fold(const float* __restrict__ Wl0, const float* __restrict__ gl0,
                       const float* __restrict__ bl0, const float* __restrict__ Wf0,
                       const float* __restrict__ gf0, const float* __restrict__ bf0,
                       const float* __restrict__ W1) {
    const int t = threadIdx.x;   // 64 threads
    if (t < 32) {
        const int i = t;
        float T1[3], T2[3][3];
#pragma unroll
        for (int c = 0; c < 3; c++)
            T1[c] = g_acc[OFF_SG1 + c] - 32.f * g_acc[OFF_SN1 + c];
#pragma unroll
        for (int aa = 0; aa < 3; aa++)
#pragma unroll
            for (int bb = 0; bb < 3; bb++)
                T2[aa][bb] = g_acc[OFF_SG2 + symi(aa, bb)]
                           - g_acc[OFF_C + aa * 3 + bb] - g_acc[OFF_C + bb * 3 + aa]
                           + 32.f * g_acc[OFF_SN2 + symi(aa, bb)];
        const float wv[3] = {Wl0[i * 3 + 0], Wl0[i * 3 + 1], Wl0[i * 3 + 2]};
        const float mL = (wv[0] * T1[0] + wv[1] * T1[1] + wv[2] * T1[2]) * CNT_INV;
        float el2 = 0.f;
#pragma unroll
        for (int aa = 0; aa < 3; aa++)
#pragma unroll
            for (int bb = 0; bb < 3; bb++) el2 = fmaf(wv[aa] * wv[bb], T2[aa][bb], el2);
        el2 *= CNT_INV;
        const float vL = fmaxf(el2 - mL * mL, 0.f);
        const float sL = gl0[i] * rsqrtf(vL + BN_EPS);

        const float mF = g_acc[OFF_SF + i] * CNT_INV;
        const float vF = fmaxf(g_acc[OFF_QF + i] * CNT_INV - mF * mF, 0.f);
        const float sF = gf0[i] * rsqrtf(vF + BN_EPS);

        float w19[20];
#pragma unroll
        for (int c = 0; c < 3; c++)  w19[c]     = sL * wv[c];
#pragma unroll
        for (int c = 0; c < 16; c++) w19[3 + c] = sF * Wf0[i * 16 + c];
        w19[19] = bl0[i] - sL * mL + bf0[i] - sF * mF;   // bias paired with constant 1.0 input
        float2* s1 = (float2*)g_stage1;
#pragma unroll
        for (int j = 0; j < 10; j++)
            s1[i * 10 + j] = make_float2(w19[2 * j], w19[2 * j + 1]);
    }
    for (int j = t; j < 1024; j += 64) {
        const int i = j >> 5, l = j & 31;
        g_stage2[j] = make_float2(W1[(2 * l) * 32 + i], W1[(2 * l + 1) * 32 + i]);
    }
}

// ---------------- gather helper: pack one sample's 19 inputs + const-1 into x2[10] ----------------
__device__ __forceinline__ void load_x2(const float* __restrict__ xyz,
                                        const float* __restrict__ pts,
                                        int n, int g, float2* x2) {
    const float c0 = __ldg(&xyz[n * 3 + 0]);
    const float c1 = __ldg(&xyz[n * 3 + 1]);
    const float c2 = __ldg(&xyz[n * 3 + 2]);
    const float d0 = __ldg(&xyz[g * 3 + 0]) - c0;
    const float d1 = __ldg(&xyz[g * 3 + 1]) - c1;
    const float d2 = __ldg(&xyz[g * 3 + 2]) - c2;
    const float4* pr = (const float4*)pts + (size_t)g * 4;
    const float4 p0 = __ldg(pr + 0), p1 = __ldg(pr + 1);
    const float4 p2 = __ldg(pr + 2), p3 = __ldg(pr + 3);
    x2[0] = make_float2(d0,   d1);
    x2[1] = make_float2(d2,   p0.x);
    x2[2] = make_float2(p0.y, p0.z);
    x2[3] = make_float2(p0.w, p1.x);
    x2[4] = make_float2(p1.y, p1.z);
    x2[5] = make_float2(p1.w, p2.x);
    x2[6] = make_float2(p2.y, p2.z);
    x2[7] = make_float2(p2.w, p3.x);
    x2[8] = make_float2(p3.y, p3.z);
    x2[9] = make_float2(p3.w, 1.f);   // constant-1 slot carries the bias
}

// ---------------- kernel 4: main fused pass (software-pipelined) ----------------
// Lane = neighbor k. Two-stage prefetch: next point's gidx is loaded before the
// current layer-1, and its 19 gather loads are issued before the layer-2 FMA
// block, whose ~1350 instructions hide the L2 latency. No hot-loop shuffles.
__global__ __launch_bounds__(128, 3)
void k_main(const float* __restrict__ xyz, const float* __restrict__ pts,
            const int* __restrict__ gidx) {
    __shared__ float4 sw1[160];          // 2.5 KB
    __shared__ float  sh[4][32 * 72];    // 36.8 KB, per-warp dup'd h, row stride 72 floats
    const int lane = threadIdx.x & 31;
    const int wib  = threadIdx.x >> 5;

    for (int t = threadIdx.x; t < 160; t += 128) sw1[t] = g_stage1[t];
    __syncthreads();

    float2 w2r[32];
#pragma unroll
    for (int i = 0; i < 32; i++) w2r[i] = __ldg(&g_stage2[i * 32 + lane]);

    float* hrow = &sh[wib][lane * 72];
    const float* hbase = sh[wib];

    float2 stat_s = make_float2(0.f, 0.f), stat_q = make_float2(0.f, 0.f);

    const int stride = GRID_MAIN * 4;
    int n = blockIdx.x * 4 + wib;
    bool valid = (n < NPTS);

    float2 x2[10];
    if (valid) {
        const int g = gidx[n * KNB + lane];
        load_x2(xyz, pts, n, g, x2);
    }

    while (valid) {
        const int n2 = n + stride;
        const bool valid2 = (n2 < NPTS);
        int g2 = 0;
        if (valid2) g2 = gidx[n2 * KNB + lane];   // prefetch index early

        // layer 1: h[i] for i=0..31, stored duplicated with granule swizzle
#pragma unroll
        for (int i2 = 0; i2 < 16; i2++) {
            float h[2];
#pragma unroll
            for (int u = 0; u < 2; u++) {
                const int i = 2 * i2 + u;
                float2 acc = make_float2(0.f, 0.f);
#pragma unroll
                for (int q = 0; q < 5; q++) {
                    const float4 w = sw1[i * 5 + q];
                    ffma2(acc, make_float2(w.x, w.y), x2[2 * q]);
                    ffma2(acc, make_float2(w.z, w.w), x2[2 * q + 1]);
                }
                h[u] = fmaxf(acc.x + acc.y, 0.f);
            }
            const int c = (i2 + lane) & 15;
            *(float4*)(hrow + c * 4) = make_float4(h[0], h[0], h[1], h[1]);
        }
        __syncwarp();

        // prefetch next point's gathers; consumed only after layer 2
        float2 x2n[10];
        if (valid2) load_x2(xyz, pts, n2, g2, x2n);

        // layer 2: lane owns outputs (2l, 2l+1); weights in regs; h via broadcast LDS.128
        float2 maxv = make_float2(-FLT_MAX, -FLT_MAX);
        float2 minv = make_float2( FLT_MAX,  FLT_MAX);
#pragma unroll 2
        for (int k = 0; k < KNB; k++) {
            const float* hr = hbase + k * 72;
            float2 z = make_float2(0.f, 0.f);
#pragma unroll
            for (int j = 0; j < 16; j++) {
                const float4 q = *(const float4*)(hr + (((j + k) & 15) * 4));
                ffma2(z, w2r[2 * j],     make_float2(q.x, q.y));
                ffma2(z, w2r[2 * j + 1], make_float2(q.z, q.w));
            }
            maxv.x = fmaxf(maxv.x, z.x); maxv.y = fmaxf(maxv.y, z.y);
            minv.x = fminf(minv.x, z.x); minv.y = fminf(minv.y, z.y);
            stat_s.x += z.x; stat_s.y += z.y;
            ffma2(stat_q, z, z);
        }
        __syncwarp();

        ((float2*)(g_zmax + (size_t)n * 64))[lane] = maxv;
        ((float2*)(g_zmin + (size_t)n * 64))[lane] = minv;

#pragma unroll
        for (int j = 0; j < 10; j++) x2[j] = x2n[j];
        n = n2;
        valid = valid2;
    }

    atomicAdd(&g_acc[OFF_S2 + 2 * lane],     stat_s.x);
    atomicAdd(&g_acc[OFF_S2 + 2 * lane + 1], stat_s.y);
    atomicAdd(&g_acc[OFF_Q2 + 2 * lane],     stat_q.x);
    atomicAdd(&g_acc[OFF_Q2 + 2 * lane + 1], stat_q.y);
}

// ---------------- kernel 5: finalize ----------------
__global__ __launch_bounds__(256)
void k_final(const float* __restrict__ g1, const float* __restrict__ beta1,
             float* __restrict__ out) {
    const int idx = blockIdx.x * blockDim.x + threadIdx.x;
    if (idx >= NPTS * 64) return;
    const int o = idx & 63;
    const float m = g_acc[OFF_S2 + o] * CNT_INV;
    const float v = fmaxf(g_acc[OFF_Q2 + o] * CNT_INV - m * m, 0.f);
    const float s = g1[o] * rsqrtf(v + BN_EPS);
    const float c = beta1[o] - s * m;
    const float z = (s >= 0.f) ? g_zmax[idx] : g_zmin[idx];
    out[idx] = fmaxf(fmaf(s, z, c), 0.f);
}

// ---------------- launch ----------------
extern "C" void kernel_launch(void* const* d_in, const int* in_sizes, int n_in,
                              void* d_out, int out_size) {
    const float* xyz   = (const float*)d_in[0];
    const float* pts   = (const float*)d_in[1];
    const int*   gidx  = (const int*)  d_in[2];
    const float* Wl0   = (const float*)d_in[3];
    const float* gl0   = (const float*)d_in[4];
    const float* bl0   = (const float*)d_in[5];
    const float* Wf0   = (const float*)d_in[6];
    const float* gf0   = (const float*)d_in[7];
    const float* bf0   = (const float*)d_in[8];
    const float* W1    = (const float*)d_in[9];
    // d_in[10] = b1: cancels inside BN2 (mean subtraction) — unused.
    const float* g1    = (const float*)d_in[11];
    const float* beta1 = (const float*)d_in[12];
    float* out = (float*)d_out;

    k_init<<<NPTS / 256, 256>>>();
    k_hc<<<512, 256>>>(xyz, gidx);
    k_mom<<<NPTS / 256, 256>>>(xyz, pts, Wf0);
    k_fold<<<1, 64>>>(Wl0, gl0, bl0, Wf0, gf0, bf0, W1);
    k_main<<<GRID_MAIN, 128>>>(xyz, pts, gidx);
    k_final<<<(NPTS * 64 + 255) / 256, 256>>>(g1, beta1, out);
}

// round 11
// speedup vs baseline: 1.2432x; 1.2432x over previous
#include <cuda_runtime.h>
#include <cfloat>

#define NPTS    65536
#define KNB     32
#define NSAMP   (NPTS * KNB)
#define CNT_INV (1.0f / 2097152.0f)
#define BN_EPS  1e-5f
#define GRID_MAIN 592
#define HSTRIDE 36   // h row stride in floats: 32 + 4 pad -> conflict-free STS.128/LDS.128

// g_acc float layout: C[9] | SG1[3] | SG2[6] | SN1[3] | SN2[6] | SF[32] | QF[32] | S2[64] | Q2[64]
#define OFF_C    0
#define OFF_SG1  9
#define OFF_SG2  12
#define OFF_SN1  18
#define OFF_SN2  21
#define OFF_SF   27
#define OFF_QF   59
#define OFF_S2   91
#define OFF_Q2   155
#define ACC_SZ   219

__device__ float  g_acc[ACC_SZ];
__device__ int    g_cnt[NPTS];
__device__ float  g_zmax[NPTS * 64];
__device__ float  g_zmin[NPTS * 64];
__device__ float4 g_stage1[160];            // layer1 folded weights, [i][5 float4] = 10 (w,w') pairs

__device__ __forceinline__ void ffma2(float2& acc, float2 a, float2 b) {
#if defined(__CUDA_ARCH__) && (__CUDA_ARCH__ >= 1000)
    union { float2 f; unsigned long long u; } A, B, C;
    A.f = a; B.f = b; C.f = acc;
    asm("fma.rn.f32x2 %0, %1, %2, %0;" : "+l"(C.u) : "l"(A.u), "l"(B.u));
    acc = C.f;
#else
    acc.x = fmaf(a.x, b.x, acc.x);
    acc.y = fmaf(a.y, b.y, acc.y);
#endif
}

// ---------------- kernel 0: zero accumulators + histogram ----------------
__global__ void k_init() {
    const int t = blockIdx.x * blockDim.x + threadIdx.x;
    if (t < NPTS) g_cnt[t] = 0;
    if (t < ACC_SZ) g_acc[t] = 0.f;
}

// ---------------- kernel 1: histogram + cross term C = sum x_g x_n^T ----------------
__global__ __launch_bounds__(256)
void k_hc(const float* __restrict__ xyz, const int* __restrict__ gidx) {
    __shared__ float sC[9];
    const int tid = threadIdx.x;
    if (tid < 9) sC[tid] = 0.f;
    __syncthreads();

    const int t0     = blockIdx.x * blockDim.x + tid;
    const int stride = gridDim.x * blockDim.x;
    float C[9];
#pragma unroll
    for (int j = 0; j < 9; j++) C[j] = 0.f;

    for (int s = t0; s < NSAMP; s += stride) {
        const int g = gidx[s];
        atomicAdd(&g_cnt[g], 1);
        const int n = s >> 5;   // warp-uniform
        const float n0 = __ldg(&xyz[n * 3 + 0]);
        const float n1 = __ldg(&xyz[n * 3 + 1]);
        const float n2 = __ldg(&xyz[n * 3 + 2]);
        const float a0 = __ldg(&xyz[g * 3 + 0]);
        const float a1 = __ldg(&xyz[g * 3 + 1]);
        const float a2 = __ldg(&xyz[g * 3 + 2]);
        C[0] = fmaf(a0, n0, C[0]); C[1] = fmaf(a0, n1, C[1]); C[2] = fmaf(a0, n2, C[2]);
        C[3] = fmaf(a1, n0, C[3]); C[4] = fmaf(a1, n1, C[4]); C[5] = fmaf(a1, n2, C[5]);
        C[6] = fmaf(a2, n0, C[6]); C[7] = fmaf(a2, n1, C[7]); C[8] = fmaf(a2, n2, C[8]);
    }
#pragma unroll
    for (int j = 0; j < 9; j++)
#pragma unroll
        for (int o = 16; o > 0; o >>= 1) C[j] += __shfl_xor_sync(0xffffffffu, C[j], o);
    if ((tid & 31) == 0)
#pragma unroll
        for (int j = 0; j < 9; j++) atomicAdd(&sC[j], C[j]);
    __syncthreads();
    if (tid < 9) atomicAdd(&g_acc[OFF_C + tid], sC[tid]);
}

// ---------------- kernel 2: cnt-weighted moments over unique points ----------------
__global__ __launch_bounds__(256)
void k_mom(const float* __restrict__ xyz, const float* __restrict__ pts,
           const float* __restrict__ Wf0) {
    __shared__ float sA[82];
    const int tid = threadIdx.x;
    if (tid < 82) sA[tid] = 0.f;
    __syncthreads();

    const int g = blockIdx.x * blockDim.x + tid;   // exactly NPTS threads
    float a[82];
#pragma unroll
    for (int j = 0; j < 82; j++) a[j] = 0.f;

    if (g < NPTS) {
        const float w  = (float)g_cnt[g];
        const float x0 = xyz[g * 3 + 0], x1 = xyz[g * 3 + 1], x2 = xyz[g * 3 + 2];
        // sg1(0..2), sg2(3..8) as (00,01,02,11,12,22), sn1(9..11), sn2(12..17), sF(18..49), qF(50..81)
        a[0] = w * x0; a[1] = w * x1; a[2] = w * x2;
        a[3] = w * x0 * x0; a[4] = w * x0 * x1; a[5] = w * x0 * x2;
        a[6] = w * x1 * x1; a[7] = w * x1 * x2; a[8] = w * x2 * x2;
        a[9] = x0; a[10] = x1; a[11] = x2;
        a[12] = x0 * x0; a[13] = x0 * x1; a[14] = x0 * x2;
        a[15] = x1 * x1; a[16] = x1 * x2; a[17] = x2 * x2;
        float p[16];
        const float4* pr = (const float4*)pts + (size_t)g * 4;
#pragma unroll
        for (int q = 0; q < 4; q++) {
            const float4 v = __ldg(pr + q);
            p[q * 4 + 0] = v.x; p[q * 4 + 1] = v.y; p[q * 4 + 2] = v.z; p[q * 4 + 3] = v.w;
        }
#pragma unroll
        for (int i = 0; i < 32; i++) {
            float f = 0.f;
#pragma unroll
            for (int c = 0; c < 16; c++) f = fmaf(__ldg(&Wf0[i * 16 + c]), p[c], f);
            a[18 + i] = w * f;
            a[50 + i] = w * f * f;
        }
    }
#pragma unroll
    for (int j = 0; j < 82; j++)
#pragma unroll
        for (int o = 16; o > 0; o >>= 1) a[j] += __shfl_xor_sync(0xffffffffu, a[j], o);
    if ((tid & 31) == 0)
#pragma unroll
        for (int j = 0; j < 82; j++) atomicAdd(&sA[j], a[j]);
    __syncthreads();
    if (tid < 82) atomicAdd(&g_acc[OFF_SG1 + tid], sA[tid]);
}

// ---------------- kernel 3: fold BN1, stage layer-1 weights ----------------
// Symmetric 3x3 pack order: (0,0)=0 (0,1)=1 (0,2)=2 (1,1)=3 (1,2)=4 (2,2)=5
__device__ __forceinline__ int symi(int aa, int bb) {
    const int lo = min(aa, bb), hi = max(aa, bb);
    return (lo == 0) ? hi : ((lo == 1) ? (2 + hi) : 5);
}

__global__ void k_fold(const float* __restrict__ Wl0, const float* __restrict__ gl0,
                       const float* __restrict__ bl0, const float* __restrict__ Wf0,
                       const float* __restrict__ gf0, const float* __restrict__ bf0) {
    const int i = threadIdx.x;   // 32 threads
    if (i >= 32) return;
    float T1[3], T2[3][3];
#pragma unroll
    for (int c = 0; c < 3; c++)
        T1[c] = g_acc[OFF_SG1 + c] - 32.f * g_acc[OFF_SN1 + c];
#pragma unroll
    for (int aa = 0; aa < 3; aa++)
#pragma unroll
        for (int bb = 0; bb < 3; bb++)
            T2[aa][bb] = g_acc[OFF_SG2 + symi(aa, bb)]
                       - g_acc[OFF_C + aa * 3 + bb] - g_acc[OFF_C + bb * 3 + aa]
                       + 32.f * g_acc[OFF_SN2 + symi(aa, bb)];
    const float wv[3] = {Wl0[i * 3 + 0], Wl0[i * 3 + 1], Wl0[i * 3 + 2]};
    const float mL = (wv[0] * T1[0] + wv[1] * T1[1] + wv[2] * T1[2]) * CNT_INV;
    float el2 = 0.f;
#pragma unroll
    for (int aa = 0; aa < 3; aa++)
#pragma unroll
        for (int bb = 0; bb < 3; bb++) el2 = fmaf(wv[aa] * wv[bb], T2[aa][bb], el2);
    el2 *= CNT_INV;
    const float vL = fmaxf(el2 - mL * mL, 0.f);
    const float sL = gl0[i] * rsqrtf(vL + BN_EPS);

    const float mF = g_acc[OFF_SF + i] * CNT_INV;
    const float vF = fmaxf(g_acc[OFF_QF + i] * CNT_INV - mF * mF, 0.f);
    const float sF = gf0[i] * rsqrtf(vF + BN_EPS);

    float w19[20];
#pragma unroll
    for (int c = 0; c < 3; c++)  w19[c]     = sL * wv[c];
#pragma unroll
    for (int c = 0; c < 16; c++) w19[3 + c] = sF * Wf0[i * 16 + c];
    w19[19] = bl0[i] - sL * mL + bf0[i] - sF * mF;   // bias paired with constant 1.0 input
    float2* s1 = (float2*)g_stage1;
#pragma unroll
    for (int j = 0; j < 10; j++)
        s1[i * 10 + j] = make_float2(w19[2 * j], w19[2 * j + 1]);
}

// ---------------- kernel 4: main fused pass ----------------
// Lane = neighbor k. Layer 1 sample-major (weights via broadcast LDS.128, bias via
// const-1 pair). h stored PLAIN (no duplication) in stride-36 rows. Layer 2:
// lane owns outputs (lane, lane+32); weights as i-pair float2s straight from W1;
// each broadcast LDS.128 of h yields two aligned (h2t,h2t+1) register pairs that
// feed f32x2 FMA directly — no dup stores, no MOVs, no shuffles.
__global__ __launch_bounds__(128, 4)
void k_main(const float* __restrict__ xyz, const float* __restrict__ pts,
            const int* __restrict__ gidx, const float* __restrict__ W1) {
    __shared__ float4 sw1[160];               // 2.5 KB
    __shared__ float  sh[4][32 * HSTRIDE];    // 18 KB, per-warp h, rows of 36 floats
    const int lane = threadIdx.x & 31;
    const int wib  = threadIdx.x >> 5;

    for (int t = threadIdx.x; t < 160; t += 128) sw1[t] = g_stage1[t];
    __syncthreads();

    // layer-2 weights, i-pair packed: wA[t] = (W1[lane][2t], W1[lane][2t+1])
    float2 wA[16], wB[16];
    {
        const float2* rA = (const float2*)(W1 + lane * 32);
        const float2* rB = (const float2*)(W1 + (lane + 32) * 32);
#pragma unroll
        for (int t = 0; t < 16; t++) { wA[t] = __ldg(rA + t); wB[t] = __ldg(rB + t); }
    }

    float* hrow = &sh[wib][lane * HSTRIDE];
    const float* hbase = sh[wib];

    float sumA = 0.f, sqA = 0.f, sumB = 0.f, sqB = 0.f;

    for (int n = blockIdx.x * 4 + wib; n < NPTS; n += GRID_MAIN * 4) {
        const int g = gidx[n * KNB + lane];
        float2 x2[10];
        {
            const float c0 = __ldg(&xyz[n * 3 + 0]);
            const float c1 = __ldg(&xyz[n * 3 + 1]);
            const float c2 = __ldg(&xyz[n * 3 + 2]);
            const float d0 = __ldg(&xyz[g * 3 + 0]) - c0;
            const float d1 = __ldg(&xyz[g * 3 + 1]) - c1;
            const float d2 = __ldg(&xyz[g * 3 + 2]) - c2;
            const float4* pr = (const float4*)pts + (size_t)g * 4;
            const float4 p0 = __ldg(pr + 0), p1 = __ldg(pr + 1);
            const float4 p2 = __ldg(pr + 2), p3 = __ldg(pr + 3);
            x2[0] = make_float2(d0,   d1);
            x2[1] = make_float2(d2,   p0.x);
            x2[2] = make_float2(p0.y, p0.z);
            x2[3] = make_float2(p0.w, p1.x);
            x2[4] = make_float2(p1.y, p1.z);
            x2[5] = make_float2(p1.w, p2.x);
            x2[6] = make_float2(p2.y, p2.z);
            x2[7] = make_float2(p2.w, p3.x);
            x2[8] = make_float2(p3.y, p3.z);
            x2[9] = make_float2(p3.w, 1.f);   // constant-1 slot carries the bias
        }

        // layer 1: 4 channels per iteration, stored as one plain float4
#pragma unroll
        for (int i4 = 0; i4 < 8; i4++) {
            float h[4];
#pragma unroll
            for (int u = 0; u < 4; u++) {
                const int i = 4 * i4 + u;
                float2 acc = make_float2(0.f, 0.f);
#pragma unroll
                for (int q = 0; q < 5; q++) {
                    const float4 w = sw1[i * 5 + q];
                    ffma2(acc, make_float2(w.x, w.y), x2[2 * q]);
                    ffma2(acc, make_float2(w.z, w.w), x2[2 * q + 1]);
                }
                h[u] = fmaxf(acc.x + acc.y, 0.f);
            }
            *(float4*)(hrow + i4 * 4) = make_float4(h[0], h[1], h[2], h[3]);
        }
        __syncwarp();

        // layer 2: z[lane] and z[lane+32]; h via broadcast LDS.128, i-pair f32x2
        float maxA = -FLT_MAX, minA = FLT_MAX, maxB = -FLT_MAX, minB = FLT_MAX;
#pragma unroll 2
        for (int k = 0; k < KNB; k++) {
            const float* hr = hbase + k * HSTRIDE;
            float2 zA = make_float2(0.f, 0.f);
            float2 zB = make_float2(0.f, 0.f);
#pragma unroll
            for (int j = 0; j < 8; j++) {
                const float4 q = *(const float4*)(hr + j * 4);
                const float2 hlo = make_float2(q.x, q.y);
                const float2 hhi = make_float2(q.z, q.w);
                ffma2(zA, wA[2 * j],     hlo);
                ffma2(zA, wA[2 * j + 1], hhi);
                ffma2(zB, wB[2 * j],     hlo);
                ffma2(zB, wB[2 * j + 1], hhi);
            }
            const float za = zA.x + zA.y;
            const float zb = zB.x + zB.y;
            maxA = fmaxf(maxA, za); minA = fminf(minA, za);
            maxB = fmaxf(maxB, zb); minB = fminf(minB, zb);
            sumA += za; sqA = fmaf(za, za, sqA);
            sumB += zb; sqB = fmaf(zb, zb, sqB);
        }
        __syncwarp();

        g_zmax[(size_t)n * 64 + lane]      = maxA;
        g_zmax[(size_t)n * 64 + 32 + lane] = maxB;
        g_zmin[(size_t)n * 64 + lane]      = minA;
        g_zmin[(size_t)n * 64 + 32 + lane] = minB;
    }

    atomicAdd(&g_acc[OFF_S2 + lane],      sumA);
    atomicAdd(&g_acc[OFF_S2 + 32 + lane], sumB);
    atomicAdd(&g_acc[OFF_Q2 + lane],      sqA);
    atomicAdd(&g_acc[OFF_Q2 + 32 + lane], sqB);
}

// ---------------- kernel 5: finalize ----------------
__global__ __launch_bounds__(256)
void k_final(const float* __restrict__ g1, const float* __restrict__ beta1,
             float* __restrict__ out) {
    const int idx = blockIdx.x * blockDim.x + threadIdx.x;
    if (idx >= NPTS * 64) return;
    const int o = idx & 63;
    const float m = g_acc[OFF_S2 + o] * CNT_INV;
    const float v = fmaxf(g_acc[OFF_Q2 + o] * CNT_INV - m * m, 0.f);
    const float s = g1[o] * rsqrtf(v + BN_EPS);
    const float c = beta1[o] - s * m;
    const float z = (s >= 0.f) ? g_zmax[idx] : g_zmin[idx];
    out[idx] = fmaxf(fmaf(s, z, c), 0.f);
}

// ---------------- launch ----------------
extern "C" void kernel_launch(void* const* d_in, const int* in_sizes, int n_in,
                              void* d_out, int out_size) {
    const float* xyz   = (const float*)d_in[0];
    const float* pts   = (const float*)d_in[1];
    const int*   gidx  = (const int*)  d_in[2];
    const float* Wl0   = (const float*)d_in[3];
    const float* gl0   = (const float*)d_in[4];
    const float* bl0   = (const float*)d_in[5];
    const float* Wf0   = (const float*)d_in[6];
    const float* gf0   = (const float*)d_in[7];
    const float* bf0   = (const float*)d_in[8];
    const float* W1    = (const float*)d_in[9];
    // d_in[10] = b1: cancels inside BN2 (mean subtraction) — unused.
    const float* g1    = (const float*)d_in[11];
    const float* beta1 = (const float*)d_in[12];
    float* out = (float*)d_out;

    k_init<<<NPTS / 256, 256>>>();
    k_hc<<<512, 256>>>(xyz, gidx);
    k_mom<<<NPTS / 256, 256>>>(xyz, pts, Wf0);
    k_fold<<<1, 32>>>(Wl0, gl0, bl0, Wf0, gf0, bf0);
    k_main<<<GRID_MAIN, 128>>>(xyz, pts, gidx, W1);
    k_final<<<(NPTS * 64 + 255) / 256, 256>>>(g1, beta1, out);
}

// round 13
// speedup vs baseline: 1.5842x; 1.2742x over previous
#include <cuda_runtime.h>
#include <cuda_bf16.h>
#include <cfloat>

#define NPTS    65536
#define KNB     32
#define NSAMP   (NPTS * KNB)
#define CNT_INV (1.0f / 2097152.0f)
#define BN_EPS  1e-5f
#define GRID_MAIN 296

// g_acc float layout: C[9] | SG1[3] | SG2[6] | SN1[3] | SN2[6] | SF[32] | QF[32] | S2[64] | Q2[64]
#define OFF_C    0
#define OFF_SG1  9
#define OFF_SG2  12
#define OFF_SN1  18
#define OFF_SN2  21
#define OFF_SF   27
#define OFF_QF   59
#define OFF_S2   91
#define OFF_Q2   155
#define ACC_SZ   219

__device__ float  g_acc[ACC_SZ];
__device__ int    g_cnt[NPTS];
__device__ float  g_zmax[NPTS * 64];
__device__ float  g_zmin[NPTS * 64];
__device__ float4 g_stage1[160];               // layer1 folded weights, [i][5 float4]
__device__ __nv_bfloat16 g_w2hi[2048];         // W1 bf16 hi, [o][i] row-major
__device__ __nv_bfloat16 g_w2lo[2048];         // W1 bf16 lo (residual)

__device__ __forceinline__ void ffma2(float2& acc, float2 a, float2 b) {
#if defined(__CUDA_ARCH__) && (__CUDA_ARCH__ >= 1000)
    union { float2 f; unsigned long long u; } A, B, C;
    A.f = a; B.f = b; C.f = acc;
    asm("fma.rn.f32x2 %0, %1, %2, %0;" : "+l"(C.u) : "l"(A.u), "l"(B.u));
    acc = C.f;
#else
    acc.x = fmaf(a.x, b.x, acc.x);
    acc.y = fmaf(a.y, b.y, acc.y);
#endif
}

// m16n8k16 bf16 MMA, fp32 accumulate in-place
__device__ __forceinline__ void mma16816(float* d, const unsigned int* a, const unsigned int* b) {
    asm volatile(
        "mma.sync.aligned.m16n8k16.row.col.f32.bf16.bf16.f32 "
        "{%0,%1,%2,%3}, {%4,%5,%6,%7}, {%8,%9}, {%0,%1,%2,%3};"
        : "+f"(d[0]), "+f"(d[1]), "+f"(d[2]), "+f"(d[3])
        : "r"(a[0]), "r"(a[1]), "r"(a[2]), "r"(a[3]), "r"(b[0]), "r"(b[1]));
}

// smem row word-offset: stride 20 words + 1 per 8 rows.
// roff(lane) mod 32 enumerates all 32 banks exactly once -> STS.32 and the
// fragment LDS.32 loads are conflict-free. (Odd bases for rows 8-15/24-31,
// so all accesses must be 32-bit — no uint2/LDS.64 on these rows!)
__device__ __forceinline__ int roff(int r) { return r * 20 + (r >> 3); }

// ---------------- kernel 0: zero accumulators + histogram ----------------
__global__ void k_init() {
    const int t = blockIdx.x * blockDim.x + threadIdx.x;
    if (t < NPTS) g_cnt[t] = 0;
    if (t < ACC_SZ) g_acc[t] = 0.f;
}

// ---------------- kernel 1: histogram + cross term C = sum x_g x_n^T ----------------
__global__ __launch_bounds__(256)
void k_hc(const float* __restrict__ xyz, const int* __restrict__ gidx) {
    __shared__ float sC[9];
    const int tid = threadIdx.x;
    if (tid < 9) sC[tid] = 0.f;
    __syncthreads();

    const int t0     = blockIdx.x * blockDim.x + tid;
    const int stride = gridDim.x * blockDim.x;
    float C[9];
#pragma unroll
    for (int j = 0; j < 9; j++) C[j] = 0.f;

    for (int s = t0; s < NSAMP; s += stride) {
        const int g = gidx[s];
        atomicAdd(&g_cnt[g], 1);
        const int n = s >> 5;   // warp-uniform
        const float n0 = __ldg(&xyz[n * 3 + 0]);
        const float n1 = __ldg(&xyz[n * 3 + 1]);
        const float n2 = __ldg(&xyz[n * 3 + 2]);
        const float a0 = __ldg(&xyz[g * 3 + 0]);
        const float a1 = __ldg(&xyz[g * 3 + 1]);
        const float a2 = __ldg(&xyz[g * 3 + 2]);
        C[0] = fmaf(a0, n0, C[0]); C[1] = fmaf(a0, n1, C[1]); C[2] = fmaf(a0, n2, C[2]);
        C[3] = fmaf(a1, n0, C[3]); C[4] = fmaf(a1, n1, C[4]); C[5] = fmaf(a1, n2, C[5]);
        C[6] = fmaf(a2, n0, C[6]); C[7] = fmaf(a2, n1, C[7]); C[8] = fmaf(a2, n2, C[8]);
    }
#pragma unroll
    for (int j = 0; j < 9; j++)
#pragma unroll
        for (int o = 16; o > 0; o >>= 1) C[j] += __shfl_xor_sync(0xffffffffu, C[j], o);
    if ((tid & 31) == 0)
#pragma unroll
        for (int j = 0; j < 9; j++) atomicAdd(&sC[j], C[j]);
    __syncthreads();
    if (tid < 9) atomicAdd(&g_acc[OFF_C + tid], sC[tid]);
}

// ---------------- kernel 2: cnt-weighted moments over unique points ----------------
__global__ __launch_bounds__(256)
void k_mom(const float* __restrict__ xyz, const float* __restrict__ pts,
           const float* __restrict__ Wf0) {
    __shared__ float sA[82];
    const int tid = threadIdx.x;
    if (tid < 82) sA[tid] = 0.f;
    __syncthreads();

    const int g = blockIdx.x * blockDim.x + tid;   // exactly NPTS threads
    float a[82];
#pragma unroll
    for (int j = 0; j < 82; j++) a[j] = 0.f;

    if (g < NPTS) {
        const float w  = (float)g_cnt[g];
        const float x0 = xyz[g * 3 + 0], x1 = xyz[g * 3 + 1], x2 = xyz[g * 3 + 2];
        a[0] = w * x0; a[1] = w * x1; a[2] = w * x2;
        a[3] = w * x0 * x0; a[4] = w * x0 * x1; a[5] = w * x0 * x2;
        a[6] = w * x1 * x1; a[7] = w * x1 * x2; a[8] = w * x2 * x2;
        a[9] = x0; a[10] = x1; a[11] = x2;
        a[12] = x0 * x0; a[13] = x0 * x1; a[14] = x0 * x2;
        a[15] = x1 * x1; a[16] = x1 * x2; a[17] = x2 * x2;
        float p[16];
        const float4* pr = (const float4*)pts + (size_t)g * 4;
#pragma unroll
        for (int q = 0; q < 4; q++) {
            const float4 v = __ldg(pr + q);
            p[q * 4 + 0] = v.x; p[q * 4 + 1] = v.y; p[q * 4 + 2] = v.z; p[q * 4 + 3] = v.w;
        }
#pragma unroll
        for (int i = 0; i < 32; i++) {
            float f = 0.f;
#pragma unroll
            for (int c = 0; c < 16; c++) f = fmaf(__ldg(&Wf0[i * 16 + c]), p[c], f);
            a[18 + i] = w * f;
            a[50 + i] = w * f * f;
        }
    }
#pragma unroll
    for (int j = 0; j < 82; j++)
#pragma unroll
        for (int o = 16; o > 0; o >>= 1) a[j] += __shfl_xor_sync(0xffffffffu, a[j], o);
    if ((tid & 31) == 0)
#pragma unroll
        for (int j = 0; j < 82; j++) atomicAdd(&sA[j], a[j]);
    __syncthreads();
    if (tid < 82) atomicAdd(&g_acc[OFF_SG1 + tid], sA[tid]);
}

// ---------------- kernel 3: fold BN1, stage weights (layer1 fp32, layer2 bf16 hi/lo) ----------------
__device__ __forceinline__ int symi(int aa, int bb) {
    const int lo = min(aa, bb), hi = max(aa, bb);
    return (lo == 0) ? hi : ((lo == 1) ? (2 + hi) : 5);
}

__global__ void k_fold(const float* __restrict__ Wl0, const float* __restrict__ gl0,
                       const float* __restrict__ bl0, const float* __restrict__ Wf0,
                       const float* __restrict__ gf0, const float* __restrict__ bf0,
                       const float* __restrict__ W1) {
    const int t = threadIdx.x;   // 64 threads
    if (t < 32) {
        const int i = t;
        float T1[3], T2[3][3];
#pragma unroll
        for (int c = 0; c < 3; c++)
            T1[c] = g_acc[OFF_SG1 + c] - 32.f * g_acc[OFF_SN1 + c];
#pragma unroll
        for (int aa = 0; aa < 3; aa++)
#pragma unroll
            for (int bb = 0; bb < 3; bb++)
                T2[aa][bb] = g_acc[OFF_SG2 + symi(aa, bb)]
                           - g_acc[OFF_C + aa * 3 + bb] - g_acc[OFF_C + bb * 3 + aa]
                           + 32.f * g_acc[OFF_SN2 + symi(aa, bb)];
        const float wv[3] = {Wl0[i * 3 + 0], Wl0[i * 3 + 1], Wl0[i * 3 + 2]};
        const float mL = (wv[0] * T1[0] + wv[1] * T1[1] + wv[2] * T1[2]) * CNT_INV;
        float el2 = 0.f;
#pragma unroll
        for (int aa = 0; aa < 3; aa++)
#pragma unroll
            for (int bb = 0; bb < 3; bb++) el2 = fmaf(wv[aa] * wv[bb], T2[aa][bb], el2);
        el2 *= CNT_INV;
        const float vL = fmaxf(el2 - mL * mL, 0.f);
        const float sL = gl0[i] * rsqrtf(vL + BN_EPS);

        const float mF = g_acc[OFF_SF + i] * CNT_INV;
        const float vF = fmaxf(g_acc[OFF_QF + i] * CNT_INV - mF * mF, 0.f);
        const float sF = gf0[i] * rsqrtf(vF + BN_EPS);

        float w19[20];
#pragma unroll
        for (int c = 0; c < 3; c++)  w19[c]     = sL * wv[c];
#pragma unroll
        for (int c = 0; c < 16; c++) w19[3 + c] = sF * Wf0[i * 16 + c];
        w19[19] = bl0[i] - sL * mL + bf0[i] - sF * mF;   // bias paired with const-1 input
        float2* s1 = (float2*)g_stage1;
#pragma unroll
        for (int j = 0; j < 10; j++)
            s1[i * 10 + j] = make_float2(w19[2 * j], w19[2 * j + 1]);
    }
    // layer-2 weights: bf16 hi + residual lo, row-major [o][i]
    for (int j = t; j < 2048; j += 64) {
        const float w = W1[j];
        const __nv_bfloat16 hi = __float2bfloat16(w);
        g_w2hi[j] = hi;
        g_w2lo[j] = __float2bfloat16(w - __bfloat162float(hi));
    }
}

// ---------------- kernel 4: main fused pass (layer2 on tensor cores) ----------------
__global__ __launch_bounds__(128, 2)
void k_main(const float* __restrict__ xyz, const float* __restrict__ pts,
            const int* __restrict__ gidx) {
    __shared__ float4 sw1[160];                  // layer-1 weights, 2.5 KB
    __shared__ unsigned int hsm[4][2][648];      // per-warp H planes (hi,lo), bf16x2 words
    const int lane = threadIdx.x & 31;
    const int wib  = threadIdx.x >> 5;
    const int lq   = lane & 3;                   // l%4
    const int lg   = lane >> 2;                  // l/4

    for (int t = threadIdx.x; t < 160; t += 128) sw1[t] = g_stage1[t];
    __syncthreads();

    // B-fragments for W1 (hi and lo), kept in registers for the whole kernel.
    // b-frag (m16n8k16, col-major B): lane holds col n = lg, rows k = 2*lq+{0,1} and +8.
    unsigned int Bhi[2][8][2], Blo[2][8][2];
#pragma unroll
    for (int kt = 0; kt < 2; kt++)
#pragma unroll
        for (int nt = 0; nt < 8; nt++) {
            const int o = nt * 8 + lg;
            const int i = kt * 16 + 2 * lq;
            Bhi[kt][nt][0] = *(const unsigned int*)(g_w2hi + o * 32 + i);
            Bhi[kt][nt][1] = *(const unsigned int*)(g_w2hi + o * 32 + i + 8);
            Blo[kt][nt][0] = *(const unsigned int*)(g_w2lo + o * 32 + i);
            Blo[kt][nt][1] = *(const unsigned int*)(g_w2lo + o * 32 + i + 8);
        }

    unsigned int* hhi = hsm[wib][0];
    unsigned int* hlo = hsm[wib][1];
    const int myrow = roff(lane);

    float sumAcc[8][2], sqAcc[8][2];
#pragma unroll
    for (int nt = 0; nt < 8; nt++) { sumAcc[nt][0] = sumAcc[nt][1] = 0.f; sqAcc[nt][0] = sqAcc[nt][1] = 0.f; }

    for (int n = blockIdx.x * 4 + wib; n < NPTS; n += GRID_MAIN * 4) {
        const int g = gidx[n * KNB + lane];
        float2 x2[10];
        {
            const float c0 = __ldg(&xyz[n * 3 + 0]);
            const float c1 = __ldg(&xyz[n * 3 + 1]);
            const float c2 = __ldg(&xyz[n * 3 + 2]);
            const float d0 = __ldg(&xyz[g * 3 + 0]) - c0;
            const float d1 = __ldg(&xyz[g * 3 + 1]) - c1;
            const float d2 = __ldg(&xyz[g * 3 + 2]) - c2;
            const float4* pr = (const float4*)pts + (size_t)g * 4;
            const float4 p0 = __ldg(pr + 0), p1 = __ldg(pr + 1);
            const float4 p2 = __ldg(pr + 2), p3 = __ldg(pr + 3);
            x2[0] = make_float2(d0,   d1);
            x2[1] = make_float2(d2,   p0.x);
            x2[2] = make_float2(p0.y, p0.z);
            x2[3] = make_float2(p0.w, p1.x);
            x2[4] = make_float2(p1.y, p1.z);
            x2[5] = make_float2(p1.w, p2.x);
            x2[6] = make_float2(p2.y, p2.z);
            x2[7] = make_float2(p2.w, p3.x);
            x2[8] = make_float2(p3.y, p3.z);
            x2[9] = make_float2(p3.w, 1.f);          // const-1 slot carries the bias
        }

        __syncwarp();   // prior iteration's fragment loads done before overwriting H

        // layer 1 (scalar): 4 channels per group -> bf16 hi/lo split -> smem planes
        // (32-bit stores only: skewed rows have odd word offsets)
#pragma unroll
        for (int i4 = 0; i4 < 8; i4++) {
            float h[4];
#pragma unroll
            for (int u = 0; u < 4; u++) {
                const int i = 4 * i4 + u;
                float2 acc = make_float2(0.f, 0.f);
#pragma unroll
                for (int q = 0; q < 5; q++) {
                    const float4 w = sw1[i * 5 + q];
                    ffma2(acc, make_float2(w.x, w.y), x2[2 * q]);
                    ffma2(acc, make_float2(w.z, w.w), x2[2 * q + 1]);
                }
                h[u] = fmaxf(acc.x + acc.y, 0.f);
            }
            const __nv_bfloat162 hi01 = __floats2bfloat162_rn(h[0], h[1]);
            const __nv_bfloat162 hi23 = __floats2bfloat162_rn(h[2], h[3]);
            const float2 b01 = __bfloat1622float2(hi01);
            const float2 b23 = __bfloat1622float2(hi23);
            const __nv_bfloat162 lo01 = __floats2bfloat162_rn(h[0] - b01.x, h[1] - b01.y);
            const __nv_bfloat162 lo23 = __floats2bfloat162_rn(h[2] - b23.x, h[3] - b23.y);
            hhi[myrow + 2 * i4]     = *(const unsigned int*)&hi01;
            hhi[myrow + 2 * i4 + 1] = *(const unsigned int*)&hi23;
            hlo[myrow + 2 * i4]     = *(const unsigned int*)&lo01;
            hlo[myrow + 2 * i4 + 1] = *(const unsigned int*)&lo23;
        }
        __syncwarp();

        // A-fragments: rows lg(+8)(+16m), col-pairs kt*8 + lq (+4)
        unsigned int Ahi[2][2][4], Alo[2][2][4];
#pragma unroll
        for (int m = 0; m < 2; m++)
#pragma unroll
            for (int kt = 0; kt < 2; kt++) {
                const int r0 = roff(lg + 16 * m);
                const int r1 = roff(lg + 16 * m + 8);
                const int p  = kt * 8 + lq;
                Ahi[m][kt][0] = hhi[r0 + p];     Ahi[m][kt][1] = hhi[r1 + p];
                Ahi[m][kt][2] = hhi[r0 + p + 4]; Ahi[m][kt][3] = hhi[r1 + p + 4];
                Alo[m][kt][0] = hlo[r0 + p];     Alo[m][kt][1] = hlo[r1 + p];
                Alo[m][kt][2] = hlo[r0 + p + 4]; Alo[m][kt][3] = hlo[r1 + p + 4];
            }

        // two N-halves to bound D register pressure
#pragma unroll
        for (int half = 0; half < 2; half++) {
            float d[2][4][4];
#pragma unroll
            for (int m = 0; m < 2; m++)
#pragma unroll
                for (int nl = 0; nl < 4; nl++)
#pragma unroll
                    for (int e = 0; e < 4; e++) d[m][nl][e] = 0.f;

#pragma unroll
            for (int kt = 0; kt < 2; kt++)
#pragma unroll
                for (int m = 0; m < 2; m++)
#pragma unroll
                    for (int nl = 0; nl < 4; nl++) {
                        const int nt = half * 4 + nl;
                        mma16816(d[m][nl], Ahi[m][kt], Bhi[kt][nt]);
                        mma16816(d[m][nl], Alo[m][kt], Bhi[kt][nt]);
                        mma16816(d[m][nl], Ahi[m][kt], Blo[kt][nt]);
                    }

            // extraction: max/min over samples + lane-local stats
#pragma unroll
            for (int nl = 0; nl < 4; nl++) {
                const int nt = half * 4 + nl;
                float mx0 = fmaxf(fmaxf(d[0][nl][0], d[0][nl][2]), fmaxf(d[1][nl][0], d[1][nl][2]));
                float mx1 = fmaxf(fmaxf(d[0][nl][1], d[0][nl][3]), fmaxf(d[1][nl][1], d[1][nl][3]));
                float mn0 = fminf(fminf(d[0][nl][0], d[0][nl][2]), fminf(d[1][nl][0], d[1][nl][2]));
                float mn1 = fminf(fminf(d[0][nl][1], d[0][nl][3]), fminf(d[1][nl][1], d[1][nl][3]));

                sumAcc[nt][0] += (d[0][nl][0] + d[0][nl][2]) + (d[1][nl][0] + d[1][nl][2]);
                sumAcc[nt][1] += (d[0][nl][1] + d[0][nl][3]) + (d[1][nl][1] + d[1][nl][3]);
                sqAcc[nt][0] = fmaf(d[0][nl][0], d[0][nl][0], sqAcc[nt][0]);
                sqAcc[nt][0] = fmaf(d[0][nl][2], d[0][nl][2], sqAcc[nt][0]);
                sqAcc[nt][0] = fmaf(d[1][nl][0], d[1][nl][0], sqAcc[nt][0]);
                sqAcc[nt][0] = fmaf(d[1][nl][2], d[1][nl][2], sqAcc[nt][0]);
                sqAcc[nt][1] = fmaf(d[0][nl][1], d[0][nl][1], sqAcc[nt][1]);
                sqAcc[nt][1] = fmaf(d[0][nl][3], d[0][nl][3], sqAcc[nt][1]);
                sqAcc[nt][1] = fmaf(d[1][nl][1], d[1][nl][1], sqAcc[nt][1]);
                sqAcc[nt][1] = fmaf(d[1][nl][3], d[1][nl][3], sqAcc[nt][1]);

#pragma unroll
                for (int off = 4; off <= 16; off <<= 1) {
                    mx0 = fmaxf(mx0, __shfl_xor_sync(0xffffffffu, mx0, off));
                    mx1 = fmaxf(mx1, __shfl_xor_sync(0xffffffffu, mx1, off));
                    mn0 = fminf(mn0, __shfl_xor_sync(0xffffffffu, mn0, off));
                    mn1 = fminf(mn1, __shfl_xor_sync(0xffffffffu, mn1, off));
                }
                if (lg == nt) {
                    const int c0 = nt * 8 + 2 * lq;
                    *(float2*)(g_zmax + (size_t)n * 64 + c0) = make_float2(mx0, mx1);
                    *(float2*)(g_zmin + (size_t)n * 64 + c0) = make_float2(mn0, mn1);
                }
            }
        }
    }

    // final stats reduction + atomics
#pragma unroll
    for (int nt = 0; nt < 8; nt++)
#pragma unroll
        for (int c = 0; c < 2; c++) {
            float s = sumAcc[nt][c], q = sqAcc[nt][c];
#pragma unroll
            for (int off = 4; off <= 16; off <<= 1) {
                s += __shfl_xor_sync(0xffffffffu, s, off);
                q += __shfl_xor_sync(0xffffffffu, q, off);
            }
            if (lg == 0) {
                const int o = nt * 8 + 2 * lq + c;
                atomicAdd(&g_acc[OFF_S2 + o], s);
                atomicAdd(&g_acc[OFF_Q2 + o], q);
            }
        }
}

// ---------------- kernel 5: finalize ----------------
__global__ __launch_bounds__(256)
void k_final(const float* __restrict__ g1, const float* __restrict__ beta1,
             float* __restrict__ out) {
    const int idx = blockIdx.x * blockDim.x + threadIdx.x;
    if (idx >= NPTS * 64) return;
    const int o = idx & 63;
    const float m = g_acc[OFF_S2 + o] * CNT_INV;
    const float v = fmaxf(g_acc[OFF_Q2 + o] * CNT_INV - m * m, 0.f);
    const float s = g1[o] * rsqrtf(v + BN_EPS);
    const float c = beta1[o] - s * m;
    const float z = (s >= 0.f) ? g_zmax[idx] : g_zmin[idx];
    out[idx] = fmaxf(fmaf(s, z, c), 0.f);
}

// ---------------- launch ----------------
extern "C" void kernel_launch(void* const* d_in, const int* in_sizes, int n_in,
                              void* d_out, int out_size) {
    const float* xyz   = (const float*)d_in[0];
    const float* pts   = (const float*)d_in[1];
    const int*   gidx  = (const int*)  d_in[2];
    const float* Wl0   = (const float*)d_in[3];
    const float* gl0   = (const float*)d_in[4];
    const float* bl0   = (const float*)d_in[5];
    const float* Wf0   = (const float*)d_in[6];
    const float* gf0   = (const float*)d_in[7];
    const float* bf0   = (const float*)d_in[8];
    const float* W1    = (const float*)d_in[9];
    // d_in[10] = b1: cancels inside BN2 (mean subtraction) — unused.
    const float* g1    = (const float*)d_in[11];
    const float* beta1 = (const float*)d_in[12];
    float* out = (float*)d_out;

    k_init<<<NPTS / 256, 256>>>();
    k_hc<<<512, 256>>>(xyz, gidx);
    k_mom<<<NPTS / 256, 256>>>(xyz, pts, Wf0);
    k_fold<<<1, 64>>>(Wl0, gl0, bl0, Wf0, gf0, bf0, W1);
    k_main<<<GRID_MAIN, 128>>>(xyz, pts, gidx);
    k_final<<<(NPTS * 64 + 255) / 256, 256>>>(g1, beta1, out);
}

// round 15
// speedup vs baseline: 2.2737x; 1.4353x over previous
#include <cuda_runtime.h>
#include <cuda_bf16.h>
#include <cfloat>

#define NPTS    65536
#define KNB     32
#define NSAMP   (NPTS * KNB)
#define CNT_INV (1.0f / 2097152.0f)
#define BN_EPS  1e-5f
#define GRID_MAIN 296

// g_acc float layout: C[9] | SG1[3] | SG2[6] | SN1[3] | SN2[6] | SF[32] | QF[32] | S2[64] | Q2[64]
#define OFF_C    0
#define OFF_SG1  9
#define OFF_SG2  12
#define OFF_SN1  18
#define OFF_SN2  21
#define OFF_SF   27
#define OFF_QF   59
#define OFF_S2   91
#define OFF_Q2   155
#define ACC_SZ   219

__device__ float  g_acc[ACC_SZ];
__device__ int    g_cnt[NPTS];
__device__ float  g_zmax[NPTS * 64];
__device__ float  g_zmin[NPTS * 64];
__device__ __nv_bfloat16 g_w1hi[1024];         // layer1 folded weights bf16 hi, [i][32] (cols 20-31 zero)
__device__ __nv_bfloat16 g_w1lo[1024];         // layer1 residual lo
__device__ __nv_bfloat16 g_w2hi[2048];         // W1 bf16 hi, [o][i] row-major
__device__ __nv_bfloat16 g_w2lo[2048];         // W1 bf16 lo (residual)

// m16n8k16 bf16 MMA, fp32 accumulate in-place
__device__ __forceinline__ void mma16816(float* d, const unsigned int* a, const unsigned int* b) {
    asm volatile(
        "mma.sync.aligned.m16n8k16.row.col.f32.bf16.bf16.f32 "
        "{%0,%1,%2,%3}, {%4,%5,%6,%7}, {%8,%9}, {%0,%1,%2,%3};"
        : "+f"(d[0]), "+f"(d[1]), "+f"(d[2]), "+f"(d[3])
        : "r"(a[0]), "r"(a[1]), "r"(a[2]), "r"(a[3]), "r"(b[0]), "r"(b[1]));
}

// smem row word-offset: stride 20 words + 1 per 8 rows; roff(lane) mod 32 hits
// all 32 banks exactly once -> STS.32 / LDS.32 conflict-free. 32-bit accesses ONLY.
__device__ __forceinline__ int roff(int r) { return r * 20 + (r >> 3); }

__device__ __forceinline__ unsigned int pack_hi(float a, float b, float2& back) {
    const __nv_bfloat162 h = __floats2bfloat162_rn(a, b);
    back = __bfloat1622float2(h);
    return *(const unsigned int*)&h;
}
__device__ __forceinline__ unsigned int pack_lo(float a, float b) {
    const __nv_bfloat162 h = __floats2bfloat162_rn(a, b);
    return *(const unsigned int*)&h;
}

// ---------------- kernel 0: zero accumulators + histogram ----------------
__global__ void k_init() {
    const int t = blockIdx.x * blockDim.x + threadIdx.x;
    if (t < NPTS) g_cnt[t] = 0;
    if (t < ACC_SZ) g_acc[t] = 0.f;
}

// ---------------- kernel 1: histogram + cross term C = sum x_g x_n^T ----------------
__global__ __launch_bounds__(256)
void k_hc(const float* __restrict__ xyz, const int* __restrict__ gidx) {
    __shared__ float sC[9];
    const int tid = threadIdx.x;
    if (tid < 9) sC[tid] = 0.f;
    __syncthreads();

    const int t0     = blockIdx.x * blockDim.x + tid;
    const int stride = gridDim.x * blockDim.x;
    float C[9];
#pragma unroll
    for (int j = 0; j < 9; j++) C[j] = 0.f;

    for (int s = t0; s < NSAMP; s += stride) {
        const int g = gidx[s];
        atomicAdd(&g_cnt[g], 1);
        const int n = s >> 5;   // warp-uniform
        const float n0 = __ldg(&xyz[n * 3 + 0]);
        const float n1 = __ldg(&xyz[n * 3 + 1]);
        const float n2 = __ldg(&xyz[n * 3 + 2]);
        const float a0 = __ldg(&xyz[g * 3 + 0]);
        const float a1 = __ldg(&xyz[g * 3 + 1]);
        const float a2 = __ldg(&xyz[g * 3 + 2]);
        C[0] = fmaf(a0, n0, C[0]); C[1] = fmaf(a0, n1, C[1]); C[2] = fmaf(a0, n2, C[2]);
        C[3] = fmaf(a1, n0, C[3]); C[4] = fmaf(a1, n1, C[4]); C[5] = fmaf(a1, n2, C[5]);
        C[6] = fmaf(a2, n0, C[6]); C[7] = fmaf(a2, n1, C[7]); C[8] = fmaf(a2, n2, C[8]);
    }
#pragma unroll
    for (int j = 0; j < 9; j++)
#pragma unroll
        for (int o = 16; o > 0; o >>= 1) C[j] += __shfl_xor_sync(0xffffffffu, C[j], o);
    if ((tid & 31) == 0)
#pragma unroll
        for (int j = 0; j < 9; j++) atomicAdd(&sC[j], C[j]);
    __syncthreads();
    if (tid < 9) atomicAdd(&g_acc[OFF_C + tid], sC[tid]);
}

// ---------------- kernel 2: cnt-weighted moments over unique points ----------------
__global__ __launch_bounds__(256)
void k_mom(const float* __restrict__ xyz, const float* __restrict__ pts,
           const float* __restrict__ Wf0) {
    __shared__ float sA[82];
    const int tid = threadIdx.x;
    if (tid < 82) sA[tid] = 0.f;
    __syncthreads();

    const int g = blockIdx.x * blockDim.x + tid;   // exactly NPTS threads
    float a[82];
#pragma unroll
    for (int j = 0; j < 82; j++) a[j] = 0.f;

    if (g < NPTS) {
        const float w  = (float)g_cnt[g];
        const float x0 = xyz[g * 3 + 0], x1 = xyz[g * 3 + 1], x2 = xyz[g * 3 + 2];
        a[0] = w * x0; a[1] = w * x1; a[2] = w * x2;
        a[3] = w * x0 * x0; a[4] = w * x0 * x1; a[5] = w * x0 * x2;
        a[6] = w * x1 * x1; a[7] = w * x1 * x2; a[8] = w * x2 * x2;
        a[9] = x0; a[10] = x1; a[11] = x2;
        a[12] = x0 * x0; a[13] = x0 * x1; a[14] = x0 * x2;
        a[15] = x1 * x1; a[16] = x1 * x2; a[17] = x2 * x2;
        float p[16];
        const float4* pr = (const float4*)pts + (size_t)g * 4;
#pragma unroll
        for (int q = 0; q < 4; q++) {
            const float4 v = __ldg(pr + q);
            p[q * 4 + 0] = v.x; p[q * 4 + 1] = v.y; p[q * 4 + 2] = v.z; p[q * 4 + 3] = v.w;
        }
#pragma unroll
        for (int i = 0; i < 32; i++) {
            float f = 0.f;
#pragma unroll
            for (int c = 0; c < 16; c++) f = fmaf(__ldg(&Wf0[i * 16 + c]), p[c], f);
            a[18 + i] = w * f;
            a[50 + i] = w * f * f;
        }
    }
#pragma unroll
    for (int j = 0; j < 82; j++)
#pragma unroll
        for (int o = 16; o > 0; o >>= 1) a[j] += __shfl_xor_sync(0xffffffffu, a[j], o);
    if ((tid & 31) == 0)
#pragma unroll
        for (int j = 0; j < 82; j++) atomicAdd(&sA[j], a[j]);
    __syncthreads();
    if (tid < 82) atomicAdd(&g_acc[OFF_SG1 + tid], sA[tid]);
}

// ---------------- kernel 3: fold BN1, stage both layers' weights as bf16 hi/lo ----------------
__device__ __forceinline__ int symi(int aa, int bb) {
    const int lo = min(aa, bb), hi = max(aa, bb);
    return (lo == 0) ? hi : ((lo == 1) ? (2 + hi) : 5);
}

__global__ void k_fold(const float* __restrict__ Wl0, const float* __restrict__ gl0,
                       const float* __restrict__ bl0, const float* __restrict__ Wf0,
                       const float* __restrict__ gf0, const float* __restrict__ bf0,
                       const float* __restrict__ W1) {
    const int t = threadIdx.x;   // 64 threads
    if (t < 32) {
        const int i = t;
        float T1[3], T2[3][3];
#pragma unroll
        for (int c = 0; c < 3; c++)
            T1[c] = g_acc[OFF_SG1 + c] - 32.f * g_acc[OFF_SN1 + c];
#pragma unroll
        for (int aa = 0; aa < 3; aa++)
#pragma unroll
            for (int bb = 0; bb < 3; bb++)
                T2[aa][bb] = g_acc[OFF_SG2 + symi(aa, bb)]
                           - g_acc[OFF_C + aa * 3 + bb] - g_acc[OFF_C + bb * 3 + aa]
                           + 32.f * g_acc[OFF_SN2 + symi(aa, bb)];
        const float wv[3] = {Wl0[i * 3 + 0], Wl0[i * 3 + 1], Wl0[i * 3 + 2]};
        const float mL = (wv[0] * T1[0] + wv[1] * T1[1] + wv[2] * T1[2]) * CNT_INV;
        float el2 = 0.f;
#pragma unroll
        for (int aa = 0; aa < 3; aa++)
#pragma unroll
            for (int bb = 0; bb < 3; bb++) el2 = fmaf(wv[aa] * wv[bb], T2[aa][bb], el2);
        el2 *= CNT_INV;
        const float vL = fmaxf(el2 - mL * mL, 0.f);
        const float sL = gl0[i] * rsqrtf(vL + BN_EPS);

        const float mF = g_acc[OFF_SF + i] * CNT_INV;
        const float vF = fmaxf(g_acc[OFF_QF + i] * CNT_INV - mF * mF, 0.f);
        const float sF = gf0[i] * rsqrtf(vF + BN_EPS);

        float w20[20];
#pragma unroll
        for (int c = 0; c < 3; c++)  w20[c]     = sL * wv[c];
#pragma unroll
        for (int c = 0; c < 16; c++) w20[3 + c] = sF * Wf0[i * 16 + c];
        w20[19] = bl0[i] - sL * mL + bf0[i] - sF * mF;   // bias: const-1 input col
#pragma unroll
        for (int c = 0; c < 20; c++) {
            const float w = w20[c];
            const __nv_bfloat16 hi = __float2bfloat16(w);
            g_w1hi[i * 32 + c] = hi;
            g_w1lo[i * 32 + c] = __float2bfloat16(w - __bfloat162float(hi));
        }
#pragma unroll
        for (int c = 20; c < 32; c++) {
            g_w1hi[i * 32 + c] = __float2bfloat16(0.f);
            g_w1lo[i * 32 + c] = __float2bfloat16(0.f);
        }
    }
    // layer-2 weights: bf16 hi + residual lo, row-major [o][i]
    for (int j = t; j < 2048; j += 64) {
        const float w = W1[j];
        const __nv_bfloat16 hi = __float2bfloat16(w);
        g_w2hi[j] = hi;
        g_w2lo[j] = __float2bfloat16(w - __bfloat162float(hi));
    }
}

// ---------------- kernel 4: main fused pass (BOTH layers on tensor cores) ----------------
__global__ __launch_bounds__(128, 2)
void k_main(const float* __restrict__ xyz, const float* __restrict__ pts,
            const int* __restrict__ gidx) {
    __shared__ unsigned int hsm[4][2][648];      // per-warp X planes (hi,lo), bf16x2 words
    const int lane = threadIdx.x & 31;
    const int wib  = threadIdx.x >> 5;
    const int lq   = lane & 3;                   // l%4
    const int lg   = lane >> 2;                  // l/4

    // layer-1 B-fragments (cols = hidden channels)
    unsigned int B1hi[2][4][2], B1lo[2][4][2];
#pragma unroll
    for (int kt = 0; kt < 2; kt++)
#pragma unroll
        for (int nt = 0; nt < 4; nt++) {
            const int i = nt * 8 + lg;
            const int c = kt * 16 + 2 * lq;
            B1hi[kt][nt][0] = *(const unsigned int*)(g_w1hi + i * 32 + c);
            B1hi[kt][nt][1] = *(const unsigned int*)(g_w1hi + i * 32 + c + 8);
            B1lo[kt][nt][0] = *(const unsigned int*)(g_w1lo + i * 32 + c);
            B1lo[kt][nt][1] = *(const unsigned int*)(g_w1lo + i * 32 + c + 8);
        }
    // layer-2 B-fragments
    unsigned int B2hi[2][8][2], B2lo[2][8][2];
#pragma unroll
    for (int kt = 0; kt < 2; kt++)
#pragma unroll
        for (int nt = 0; nt < 8; nt++) {
            const int o = nt * 8 + lg;
            const int i = kt * 16 + 2 * lq;
            B2hi[kt][nt][0] = *(const unsigned int*)(g_w2hi + o * 32 + i);
            B2hi[kt][nt][1] = *(const unsigned int*)(g_w2hi + o * 32 + i + 8);
            B2lo[kt][nt][0] = *(const unsigned int*)(g_w2lo + o * 32 + i);
            B2lo[kt][nt][1] = *(const unsigned int*)(g_w2lo + o * 32 + i + 8);
        }

    unsigned int* xhi = hsm[wib][0];
    unsigned int* xlo = hsm[wib][1];
    const int myrow = roff(lane);

    // zero the pad words (X cols 20..31) once
#pragma unroll
    for (int w = 10; w < 16; w++) { xhi[myrow + w] = 0u; xlo[myrow + w] = 0u; }
    __syncwarp();

    float sumAcc[8][2], sqAcc[8][2];
#pragma unroll
    for (int nt = 0; nt < 8; nt++) { sumAcc[nt][0] = sumAcc[nt][1] = 0.f; sqAcc[nt][0] = sqAcc[nt][1] = 0.f; }

    for (int n = blockIdx.x * 4 + wib; n < NPTS; n += GRID_MAIN * 4) {
        const int g = gidx[n * KNB + lane];
        float x[20];
        {
            const float c0 = __ldg(&xyz[n * 3 + 0]);
            const float c1 = __ldg(&xyz[n * 3 + 1]);
            const float c2 = __ldg(&xyz[n * 3 + 2]);
            x[0] = __ldg(&xyz[g * 3 + 0]) - c0;
            x[1] = __ldg(&xyz[g * 3 + 1]) - c1;
            x[2] = __ldg(&xyz[g * 3 + 2]) - c2;
            const float4* pr = (const float4*)pts + (size_t)g * 4;
#pragma unroll
            for (int q = 0; q < 4; q++) {
                const float4 v = __ldg(pr + q);
                x[3 + 4 * q] = v.x; x[4 + 4 * q] = v.y; x[5 + 4 * q] = v.z; x[6 + 4 * q] = v.w;
            }
            x[19] = 1.f;   // const-1 carries the bias
        }

        __syncwarp();   // prior iteration's X fragment loads done before overwrite

        // store X as bf16 hi/lo pairs (words 0..9; 10..15 are the zero pad)
#pragma unroll
        for (int j = 0; j < 10; j++) {
            float2 back;
            const unsigned int h = pack_hi(x[2 * j], x[2 * j + 1], back);
            xhi[myrow + j] = h;
            xlo[myrow + j] = pack_lo(x[2 * j] - back.x, x[2 * j + 1] - back.y);
        }
        __syncwarp();

        // X A-fragments
        unsigned int A1hi[2][2][4], A1lo[2][2][4];
#pragma unroll
        for (int m = 0; m < 2; m++)
#pragma unroll
            for (int kt = 0; kt < 2; kt++) {
                const int r0 = roff(lg + 16 * m);
                const int r1 = roff(lg + 16 * m + 8);
                const int p  = kt * 8 + lq;
                A1hi[m][kt][0] = xhi[r0 + p];     A1hi[m][kt][1] = xhi[r1 + p];
                A1hi[m][kt][2] = xhi[r0 + p + 4]; A1hi[m][kt][3] = xhi[r1 + p + 4];
                A1lo[m][kt][0] = xlo[r0 + p];     A1lo[m][kt][1] = xlo[r1 + p];
                A1lo[m][kt][2] = xlo[r0 + p + 4]; A1lo[m][kt][3] = xlo[r1 + p + 4];
            }

        // layer 1 MMA: H = X * W1d^T  (M=32 samples, N=32 hidden, K=32)
        float d1[2][4][4];
#pragma unroll
        for (int m = 0; m < 2; m++)
#pragma unroll
            for (int nt = 0; nt < 4; nt++) {
#pragma unroll
                for (int e = 0; e < 4; e++) d1[m][nt][e] = 0.f;
#pragma unroll
                for (int kt = 0; kt < 2; kt++) {
                    mma16816(d1[m][nt], A1hi[m][kt], B1hi[kt][nt]);
                    mma16816(d1[m][nt], A1lo[m][kt], B1hi[kt][nt]);
                    mma16816(d1[m][nt], A1hi[m][kt], B1lo[kt][nt]);
                }
            }

        // ReLU + register repack: D1 (m16n8 accum) -> layer-2 A-fragments (hi/lo)
        // a0 <- nt=2kt+0 (c0,c1); a2 <- nt=2kt+1 (c0,c1); a1/a3 same with (c2,c3)
        unsigned int A2hi[2][2][4], A2lo[2][2][4];
#pragma unroll
        for (int m = 0; m < 2; m++)
#pragma unroll
            for (int kt = 0; kt < 2; kt++) {
#pragma unroll
                for (int s = 0; s < 2; s++) {          // s: 0 -> a0/a1 (nt=2kt), 1 -> a2/a3 (nt=2kt+1)
                    const int nt = 2 * kt + s;
                    const float h0 = fmaxf(d1[m][nt][0], 0.f);
                    const float h1 = fmaxf(d1[m][nt][1], 0.f);
                    const float h2 = fmaxf(d1[m][nt][2], 0.f);
                    const float h3 = fmaxf(d1[m][nt][3], 0.f);
                    float2 b01, b23;
                    A2hi[m][kt][0 + 2 * s] = pack_hi(h0, h1, b01);
                    A2hi[m][kt][1 + 2 * s] = pack_hi(h2, h3, b23);
                    A2lo[m][kt][0 + 2 * s] = pack_lo(h0 - b01.x, h1 - b01.y);
                    A2lo[m][kt][1 + 2 * s] = pack_lo(h2 - b23.x, h3 - b23.y);
                }
            }

        // layer 2 MMA + extraction, two N-halves to bound D register pressure
#pragma unroll
        for (int half = 0; half < 2; half++) {
            float d[2][4][4];
#pragma unroll
            for (int m = 0; m < 2; m++)
#pragma unroll
                for (int nl = 0; nl < 4; nl++)
#pragma unroll
                    for (int e = 0; e < 4; e++) d[m][nl][e] = 0.f;

#pragma unroll
            for (int kt = 0; kt < 2; kt++)
#pragma unroll
                for (int m = 0; m < 2; m++)
#pragma unroll
                    for (int nl = 0; nl < 4; nl++) {
                        const int nt = half * 4 + nl;
                        mma16816(d[m][nl], A2hi[m][kt], B2hi[kt][nt]);
                        mma16816(d[m][nl], A2lo[m][kt], B2hi[kt][nt]);
                        mma16816(d[m][nl], A2hi[m][kt], B2lo[kt][nt]);
                    }

#pragma unroll
            for (int nl = 0; nl < 4; nl++) {
                const int nt = half * 4 + nl;
                float mx0 = fmaxf(fmaxf(d[0][nl][0], d[0][nl][2]), fmaxf(d[1][nl][0], d[1][nl][2]));
                float mx1 = fmaxf(fmaxf(d[0][nl][1], d[0][nl][3]), fmaxf(d[1][nl][1], d[1][nl][3]));
                float mn0 = fminf(fminf(d[0][nl][0], d[0][nl][2]), fminf(d[1][nl][0], d[1][nl][2]));
                float mn1 = fminf(fminf(d[0][nl][1], d[0][nl][3]), fminf(d[1][nl][1], d[1][nl][3]));

                sumAcc[nt][0] += (d[0][nl][0] + d[0][nl][2]) + (d[1][nl][0] + d[1][nl][2]);
                sumAcc[nt][1] += (d[0][nl][1] + d[0][nl][3]) + (d[1][nl][1] + d[1][nl][3]);
                sqAcc[nt][0] = fmaf(d[0][nl][0], d[0][nl][0], sqAcc[nt][0]);
                sqAcc[nt][0] = fmaf(d[0][nl][2], d[0][nl][2], sqAcc[nt][0]);
                sqAcc[nt][0] = fmaf(d[1][nl][0], d[1][nl][0], sqAcc[nt][0]);
                sqAcc[nt][0] = fmaf(d[1][nl][2], d[1][nl][2], sqAcc[nt][0]);
                sqAcc[nt][1] = fmaf(d[0][nl][1], d[0][nl][1], sqAcc[nt][1]);
                sqAcc[nt][1] = fmaf(d[0][nl][3], d[0][nl][3], sqAcc[nt][1]);
                sqAcc[nt][1] = fmaf(d[1][nl][1], d[1][nl][1], sqAcc[nt][1]);
                sqAcc[nt][1] = fmaf(d[1][nl][3], d[1][nl][3], sqAcc[nt][1]);

#pragma unroll
                for (int off = 4; off <= 16; off <<= 1) {
                    mx0 = fmaxf(mx0, __shfl_xor_sync(0xffffffffu, mx0, off));
                    mx1 = fmaxf(mx1, __shfl_xor_sync(0xffffffffu, mx1, off));
                    mn0 = fminf(mn0, __shfl_xor_sync(0xffffffffu, mn0, off));
                    mn1 = fminf(mn1, __shfl_xor_sync(0xffffffffu, mn1, off));
                }
                if (lg == nt) {
                    const int c0 = nt * 8 + 2 * lq;
                    *(float2*)(g_zmax + (size_t)n * 64 + c0) = make_float2(mx0, mx1);
                    *(float2*)(g_zmin + (size_t)n * 64 + c0) = make_float2(mn0, mn1);
                }
            }
        }
    }

    // final stats reduction + atomics
#pragma unroll
    for (int nt = 0; nt < 8; nt++)
#pragma unroll
        for (int c = 0; c < 2; c++) {
            float s = sumAcc[nt][c], q = sqAcc[nt][c];
#pragma unroll
            for (int off = 4; off <= 16; off <<= 1) {
                s += __shfl_xor_sync(0xffffffffu, s, off);
                q += __shfl_xor_sync(0xffffffffu, q, off);
            }
            if (lg == 0) {
                const int o = nt * 8 + 2 * lq + c;
                atomicAdd(&g_acc[OFF_S2 + o], s);
                atomicAdd(&g_acc[OFF_Q2 + o], q);
            }
        }
}

// ---------------- kernel 5: finalize ----------------
__global__ __launch_bounds__(256)
void k_final(const float* __restrict__ g1, const float* __restrict__ beta1,
             float* __restrict__ out) {
    const int idx = blockIdx.x * blockDim.x + threadIdx.x;
    if (idx >= NPTS * 64) return;
    const int o = idx & 63;
    const float m = g_acc[OFF_S2 + o] * CNT_INV;
    const float v = fmaxf(g_acc[OFF_Q2 + o] * CNT_INV - m * m, 0.f);
    const float s = g1[o] * rsqrtf(v + BN_EPS);
    const float c = beta1[o] - s * m;
    const float z = (s >= 0.f) ? g_zmax[idx] : g_zmin[idx];
    out[idx] = fmaxf(fmaf(s, z, c), 0.f);
}

// ---------------- launch ----------------
extern "C" void kernel_launch(void* const* d_in, const int* in_sizes, int n_in,
                              void* d_out, int out_size) {
    const float* xyz   = (const float*)d_in[0];
    const float* pts   = (const float*)d_in[1];
    const int*   gidx  = (const int*)  d_in[2];
    const float* Wl0   = (const float*)d_in[3];
    const float* gl0   = (const float*)d_in[4];
    const float* bl0   = (const float*)d_in[5];
    const float* Wf0   = (const float*)d_in[6];
    const float* gf0   = (const float*)d_in[7];
    const float* bf0   = (const float*)d_in[8];
    const float* W1    = (const float*)d_in[9];
    // d_in[10] = b1: cancels inside BN2 (mean subtraction) — unused.
    const float* g1    = (const float*)d_in[11];
    const float* beta1 = (const float*)d_in[12];
    float* out = (float*)d_out;

    k_init<<<NPTS / 256, 256>>>();
    k_hc<<<512, 256>>>(xyz, gidx);
    k_mom<<<NPTS / 256, 256>>>(xyz, pts, Wf0);
    k_fold<<<1, 64>>>(Wl0, gl0, bl0, Wf0, gf0, bf0, W1);
    k_main<<<GRID_MAIN, 128>>>(xyz, pts, gidx);
    k_final<<<(NPTS * 64 + 255) / 256, 256>>>(g1, beta1, out);
}